// round 5
// baseline (speedup 1.0000x reference)
#include <cuda_runtime.h>
#include <math.h>

// Problem constants
#define B  128
#define H  4
#define N  4096
#define W  128
#define BH (B*H)         // 512
#define CSTRIDE 1560     // 3*H*W + 6*H
#define EPS 1e-8f

// ---------------- device scratch (no allocations allowed) ----------------
__device__ float g_keys  [BH*W];
__device__ float g_write [BH*W];
__device__ float g_erase [BH*W];
__device__ float g_beta  [BH];
__device__ float g_gate  [BH];
__device__ float g_gamma [BH];
__device__ float g_keynorm[BH];
__device__ float g_shift [BH*3];
__device__ float g_prevw [H*N];
__device__ float g_scores[BH*N];
__device__ float g_wdist [BH*N];

__device__ __forceinline__ float sigmoidf_(float x){ return 1.0f/(1.0f+expf(-x)); }
__device__ __forceinline__ float softplusf_(float x){ return fmaxf(x,0.0f)+log1pf(expf(-fabsf(x))); }

// ---------------- kernel A: control transforms ----------------
// grid = BH blocks, 128 threads; block = (b,h)
__global__ void prep_kernel(const float* __restrict__ controls)
{
    int bh = blockIdx.x;
    int b  = bh >> 2, h = bh & 3;
    int w  = threadIdx.x;
    const float* c = controls + (long)b * CSTRIDE;

    float key = tanhf(c[h*W + w]);
    g_keys [bh*W + w] = key;
    g_erase[bh*W + w] = sigmoidf_(c[H*W   + h*W + w]);
    g_write[bh*W + w] = tanhf    (c[2*H*W + h*W + w]);

    // block-reduce sum of key^2 (4 warps)
    float ss = key*key;
    #pragma unroll
    for (int o = 16; o; o >>= 1) ss += __shfl_xor_sync(0xffffffffu, ss, o);
    __shared__ float red[4];
    if ((w & 31) == 0) red[w >> 5] = ss;
    __syncthreads();
    if (w == 0) {
        float s = red[0] + red[1] + red[2] + red[3];
        g_keynorm[bh] = sqrtf(s);
        g_beta[bh]  = softplusf_(c[3*H*W + h]);
        g_gate[bh]  = sigmoidf_(c[3*H*W + H + h]);
        float s0 = c[3*H*W + 2*H + h*3 + 0];
        float s1 = c[3*H*W + 2*H + h*3 + 1];
        float s2 = c[3*H*W + 2*H + h*3 + 2];
        float m  = fmaxf(s0, fmaxf(s1, s2));
        float e0 = expf(s0 - m), e1 = expf(s1 - m), e2 = expf(s2 - m);
        float inv = 1.0f / (e0 + e1 + e2);
        g_shift[bh*3 + 0] = e0 * inv;
        g_shift[bh*3 + 1] = e1 * inv;
        g_shift[bh*3 + 2] = e2 * inv;
        g_gamma[bh] = 1.0f + softplusf_(c[3*H*W + 5*H + h]);
    }
}

// ---------------- kernel A2: softmax of write_dist_bias per head ----------------
// grid = H blocks, 256 threads
__global__ void prevw_kernel(const float* __restrict__ bias)
{
    int h = blockIdx.x, t = threadIdx.x;
    const float* r = bias + h*N;
    float v[16];
    float mx = -INFINITY;
    #pragma unroll
    for (int i = 0; i < 16; i++) { v[i] = r[t + i*256]; mx = fmaxf(mx, v[i]); }

    __shared__ float red[8];
    #pragma unroll
    for (int o = 16; o; o >>= 1) mx = fmaxf(mx, __shfl_xor_sync(0xffffffffu, mx, o));
    if ((t & 31) == 0) red[t >> 5] = mx;
    __syncthreads();
    float M = red[0];
    #pragma unroll
    for (int i = 1; i < 8; i++) M = fmaxf(M, red[i]);
    __syncthreads();

    float s = 0.0f;
    #pragma unroll
    for (int i = 0; i < 16; i++) { v[i] = expf(v[i] - M); s += v[i]; }
    #pragma unroll
    for (int o = 16; o; o >>= 1) s += __shfl_xor_sync(0xffffffffu, s, o);
    if ((t & 31) == 0) red[t >> 5] = s;
    __syncthreads();
    float S = 0.0f;
    #pragma unroll
    for (int i = 0; i < 8; i++) S += red[i];
    float inv = 1.0f / S;
    #pragma unroll
    for (int i = 0; i < 16; i++) g_prevw[h*N + t + i*256] = v[i] * inv;
}

// ---------------- kernel B: scores = beta * cos(memory, key) ----------------
// Pass 1 over memory. One warp per (b,n) row, 4 rows/warp, 32 rows/block.
// All 4 row loads issued up-front (MLP_p1=4) before any reduction math.
// grid = B * N/32 = 16384, 256 threads.
__global__ void score_kernel(const float* __restrict__ memory)
{
    int b    = blockIdx.x >> 7;           // N/32 = 128 blocks per batch
    int n0   = (blockIdx.x & 127) * 32;
    int lane = threadIdx.x & 31;
    int warp = threadIdx.x >> 5;

    // per-lane key slices (fixed w = lane*4 .. +3) and per-head scalars
    const float4* K = (const float4*)g_keys;
    float4 k0 = K[((b*4 + 0)*W >> 2) + lane];
    float4 k1 = K[((b*4 + 1)*W >> 2) + lane];
    float4 k2 = K[((b*4 + 2)*W >> 2) + lane];
    float4 k3 = K[((b*4 + 3)*W >> 2) + lane];
    float be0 = g_beta[b*4+0], be1 = g_beta[b*4+1], be2 = g_beta[b*4+2], be3 = g_beta[b*4+3];
    float kn0 = g_keynorm[b*4+0], kn1 = g_keynorm[b*4+1], kn2 = g_keynorm[b*4+2], kn3 = g_keynorm[b*4+3];

    const float4* M4 = (const float4*)memory;
    int nbase = n0 + warp*4;
    long rowidx = (((long)b*N + nbase) << 5) + lane;

    // front-batch all 4 independent row loads
    float4 m0 = M4[rowidx];
    float4 m1 = M4[rowidx + 32];
    float4 m2 = M4[rowidx + 64];
    float4 m3 = M4[rowidx + 96];

    float4 mrow[4] = {m0, m1, m2, m3};
    #pragma unroll
    for (int r = 0; r < 4; r++) {
        float4 m = mrow[r];
        int n = nbase + r;
        float nn = m.x*m.x + m.y*m.y + m.z*m.z + m.w*m.w;
        float d0 = m.x*k0.x + m.y*k0.y + m.z*k0.z + m.w*k0.w;
        float d1 = m.x*k1.x + m.y*k1.y + m.z*k1.z + m.w*k1.w;
        float d2 = m.x*k2.x + m.y*k2.y + m.z*k2.z + m.w*k2.w;
        float d3 = m.x*k3.x + m.y*k3.y + m.z*k3.z + m.w*k3.w;
        #pragma unroll
        for (int o = 16; o; o >>= 1) {
            nn += __shfl_xor_sync(0xffffffffu, nn, o);
            d0 += __shfl_xor_sync(0xffffffffu, d0, o);
            d1 += __shfl_xor_sync(0xffffffffu, d1, o);
            d2 += __shfl_xor_sync(0xffffffffu, d2, o);
            d3 += __shfl_xor_sync(0xffffffffu, d3, o);
        }
        float mn = sqrtf(nn);
        if (lane < 4) {
            float dd = (lane == 0) ? d0 : (lane == 1) ? d1 : (lane == 2) ? d2 : d3;
            float be = (lane == 0) ? be0 : (lane == 1) ? be1 : (lane == 2) ? be2 : be3;
            float kn = (lane == 0) ? kn0 : (lane == 1) ? kn1 : (lane == 2) ? kn2 : kn3;
            g_scores[(b*4 + lane)*N + n] = be * dd / (kn * mn + EPS);
        }
    }
}

// ---------------- kernel C: write distribution ----------------
// grid = BH blocks (one per (b,h)), 256 threads; 16 elems/thread.
__global__ void wdist_kernel()
{
    int bh = blockIdx.x;
    int h  = bh & 3;
    int t  = threadIdx.x;
    int lane = t & 31, warp = t >> 5;

    __shared__ float sw[N];
    __shared__ float redA[8];
    __shared__ float redB[8];

    const float* sc = g_scores + bh*N;
    float v[16];
    float mx = -INFINITY;
    #pragma unroll
    for (int i = 0; i < 16; i++) { v[i] = sc[t + i*256]; mx = fmaxf(mx, v[i]); }

    // block max
    #pragma unroll
    for (int o = 16; o; o >>= 1) mx = fmaxf(mx, __shfl_xor_sync(0xffffffffu, mx, o));
    if (lane == 0) redA[warp] = mx;
    __syncthreads();
    float M = redA[0];
    #pragma unroll
    for (int i = 1; i < 8; i++) M = fmaxf(M, redA[i]);

    // exp + block sum
    float s = 0.0f;
    #pragma unroll
    for (int i = 0; i < 16; i++) { v[i] = expf(v[i] - M); s += v[i]; }
    #pragma unroll
    for (int o = 16; o; o >>= 1) s += __shfl_xor_sync(0xffffffffu, s, o);
    if (lane == 0) redB[warp] = s;
    __syncthreads();
    float S = 0.0f;
    #pragma unroll
    for (int i = 0; i < 8; i++) S += redB[i];
    float invS = 1.0f / S;

    float g  = g_gate[bh];
    float og = 1.0f - g;
    #pragma unroll
    for (int i = 0; i < 16; i++) {
        int n = t + i*256;
        sw[n] = g * v[i] * invS + og * g_prevw[h*N + n];
    }
    __syncthreads();

    float s0 = g_shift[bh*3 + 0], s1 = g_shift[bh*3 + 1], s2 = g_shift[bh*3 + 2];
    float gamma = g_gamma[bh];
    float T = 0.0f;
    #pragma unroll
    for (int i = 0; i < 16; i++) {
        int n = t + i*256;
        float ws = s0 * sw[(n + N - 1) & (N - 1)] + s1 * sw[n] + s2 * sw[(n + 1) & (N - 1)];
        v[i] = powf(ws, gamma);
        T += v[i];
    }
    #pragma unroll
    for (int o = 16; o; o >>= 1) T += __shfl_xor_sync(0xffffffffu, T, o);
    __syncthreads();           // redA reuse safe (everyone done reading M)
    if (lane == 0) redA[warp] = T;
    __syncthreads();
    float TT = 0.0f;
    #pragma unroll
    for (int i = 0; i < 8; i++) TT += redA[i];
    float invT = 1.0f / (TT + EPS);
    #pragma unroll
    for (int i = 0; i < 16; i++) g_wdist[bh*N + t + i*256] = v[i] * invT;
}

// ---------------- kernel D: memory update (erase + add) ----------------
// Pass 2 over memory. One warp per row, 4 rows/warp, 32 rows/block.
// erase/write slices live in registers (fixed per lane) -> no smem in loop.
// All memory row loads + wdist scalars front-batched.
// grid = B * N/32 = 16384, 256 threads.
__global__ void update_kernel(const float* __restrict__ memory, float* __restrict__ out)
{
    int b    = blockIdx.x >> 7;
    int n0   = (blockIdx.x & 127) * 32;
    int lane = threadIdx.x & 31;
    int warp = threadIdx.x >> 5;

    const float4* E = (const float4*)g_erase;
    const float4* Wd = (const float4*)g_write;
    float4 e0 = E[((b*4+0)*W >> 2) + lane];
    float4 e1 = E[((b*4+1)*W >> 2) + lane];
    float4 e2 = E[((b*4+2)*W >> 2) + lane];
    float4 e3 = E[((b*4+3)*W >> 2) + lane];
    float4 w0 = Wd[((b*4+0)*W >> 2) + lane];
    float4 w1 = Wd[((b*4+1)*W >> 2) + lane];
    float4 w2 = Wd[((b*4+2)*W >> 2) + lane];
    float4 w3 = Wd[((b*4+3)*W >> 2) + lane];

    const float4* M4 = (const float4*)memory;
    float4*       O4 = (float4*)out;

    int nbase = n0 + warp*4;
    long rowidx = (((long)b*N + nbase) << 5) + lane;

    // front-batch the 4 memory row loads
    float4 mrow[4];
    mrow[0] = M4[rowidx];
    mrow[1] = M4[rowidx + 32];
    mrow[2] = M4[rowidx + 64];
    mrow[3] = M4[rowidx + 96];

    // front-batch the 16 wdist scalars
    float wdv[4][4];
    #pragma unroll
    for (int r = 0; r < 4; r++) {
        int n = nbase + r;
        wdv[r][0] = g_wdist[(b*4+0)*N + n];
        wdv[r][1] = g_wdist[(b*4+1)*N + n];
        wdv[r][2] = g_wdist[(b*4+2)*N + n];
        wdv[r][3] = g_wdist[(b*4+3)*N + n];
    }

    #pragma unroll
    for (int r = 0; r < 4; r++) {
        float wd0 = wdv[r][0], wd1 = wdv[r][1], wd2 = wdv[r][2], wd3 = wdv[r][3];
        float4 m = mrow[r];
        float4 o;
        {
            float er = (1.0f - wd0*e0.x)*(1.0f - wd1*e1.x)*(1.0f - wd2*e2.x)*(1.0f - wd3*e3.x);
            float up = wd0*w0.x + wd1*w1.x + wd2*w2.x + wd3*w3.x;
            o.x = m.x*er + up;
        }
        {
            float er = (1.0f - wd0*e0.y)*(1.0f - wd1*e1.y)*(1.0f - wd2*e2.y)*(1.0f - wd3*e3.y);
            float up = wd0*w0.y + wd1*w1.y + wd2*w2.y + wd3*w3.y;
            o.y = m.y*er + up;
        }
        {
            float er = (1.0f - wd0*e0.z)*(1.0f - wd1*e1.z)*(1.0f - wd2*e2.z)*(1.0f - wd3*e3.z);
            float up = wd0*w0.z + wd1*w1.z + wd2*w2.z + wd3*w3.z;
            o.z = m.z*er + up;
        }
        {
            float er = (1.0f - wd0*e0.w)*(1.0f - wd1*e1.w)*(1.0f - wd2*e2.w)*(1.0f - wd3*e3.w);
            float up = wd0*w0.w + wd1*w1.w + wd2*w2.w + wd3*w3.w;
            o.w = m.w*er + up;
        }
        O4[rowidx + r*32] = o;
    }
}

// ---------------- launch ----------------
extern "C" void kernel_launch(void* const* d_in, const int* in_sizes, int n_in,
                              void* d_out, int out_size)
{
    const float* memory   = (const float*)d_in[0];
    const float* controls = (const float*)d_in[1];
    const float* bias     = (const float*)d_in[2];
    float* out = (float*)d_out;

    prep_kernel  <<<BH, W>>>(controls);
    prevw_kernel <<<H, 256>>>(bias);
    score_kernel <<<B * (N/32), 256>>>(memory);
    wdist_kernel <<<BH, 256>>>();
    update_kernel<<<B * (N/32), 256>>>(memory, out);
}

// round 14
// speedup vs baseline: 1.1672x; 1.1672x over previous
#include <cuda_runtime.h>
#include <math.h>

// Problem constants
#define B  128
#define H  4
#define N  4096
#define W  128
#define BH (B*H)         // 512
#define CSTRIDE 1560     // 3*H*W + 6*H
#define EPS 1e-8f

// ---------------- device scratch (no allocations allowed) ----------------
__device__ float g_keys  [BH*W];
__device__ float g_write [BH*W];
__device__ float g_erase [BH*W];
__device__ float g_beta  [BH];
__device__ float g_gate  [BH];
__device__ float g_gamma [BH];
__device__ float g_keynorm[BH];
__device__ float g_shift [BH*3];
__device__ float g_prevw [H*N];
__device__ float g_scores[BH*N];
__device__ float g_wdist [BH*N];

__device__ __forceinline__ float sigmoidf_(float x){ return 1.0f/(1.0f+expf(-x)); }
__device__ __forceinline__ float softplusf_(float x){ return fmaxf(x,0.0f)+log1pf(expf(-fabsf(x))); }

// ---------------- kernel A (merged): control transforms + bias softmax ----------------
// grid = BH + H blocks, 256 threads.
// blocks [0, BH): prep for (b,h) = block; blocks [BH, BH+H): prevw for head block-BH.
__global__ void prep_all_kernel(const float* __restrict__ controls,
                                const float* __restrict__ bias)
{
    if (blockIdx.x < BH) {
        // ---- prep path (first 128 threads do the W-wide work) ----
        int bh = blockIdx.x;
        int b  = bh >> 2, h = bh & 3;
        int w  = threadIdx.x;
        const float* c = controls + (long)b * CSTRIDE;
        __shared__ float red[4];

        if (w < 128) {
            float key = tanhf(c[h*W + w]);
            g_keys [bh*W + w] = key;
            g_erase[bh*W + w] = sigmoidf_(c[H*W   + h*W + w]);
            g_write[bh*W + w] = tanhf    (c[2*H*W + h*W + w]);

            float ss = key*key;
            #pragma unroll
            for (int o = 16; o; o >>= 1) ss += __shfl_xor_sync(0xffffffffu, ss, o);
            if ((w & 31) == 0) red[w >> 5] = ss;
        }
        __syncthreads();
        if (w == 0) {
            float s = red[0] + red[1] + red[2] + red[3];
            g_keynorm[bh] = sqrtf(s);
            g_beta[bh]  = softplusf_(c[3*H*W + h]);
            g_gate[bh]  = sigmoidf_(c[3*H*W + H + h]);
            float s0 = c[3*H*W + 2*H + h*3 + 0];
            float s1 = c[3*H*W + 2*H + h*3 + 1];
            float s2 = c[3*H*W + 2*H + h*3 + 2];
            float m  = fmaxf(s0, fmaxf(s1, s2));
            float e0 = expf(s0 - m), e1 = expf(s1 - m), e2 = expf(s2 - m);
            float inv = 1.0f / (e0 + e1 + e2);
            g_shift[bh*3 + 0] = e0 * inv;
            g_shift[bh*3 + 1] = e1 * inv;
            g_shift[bh*3 + 2] = e2 * inv;
            g_gamma[bh] = 1.0f + softplusf_(c[3*H*W + 5*H + h]);
        }
    } else {
        // ---- prevw path: softmax over bias row for head (blockIdx.x - BH) ----
        int h = blockIdx.x - BH, t = threadIdx.x;
        const float* r = bias + h*N;
        float v[16];
        float mx = -INFINITY;
        #pragma unroll
        for (int i = 0; i < 16; i++) { v[i] = r[t + i*256]; mx = fmaxf(mx, v[i]); }

        __shared__ float red8[8];
        #pragma unroll
        for (int o = 16; o; o >>= 1) mx = fmaxf(mx, __shfl_xor_sync(0xffffffffu, mx, o));
        if ((t & 31) == 0) red8[t >> 5] = mx;
        __syncthreads();
        float M = red8[0];
        #pragma unroll
        for (int i = 1; i < 8; i++) M = fmaxf(M, red8[i]);
        __syncthreads();

        float s = 0.0f;
        #pragma unroll
        for (int i = 0; i < 16; i++) { v[i] = expf(v[i] - M); s += v[i]; }
        #pragma unroll
        for (int o = 16; o; o >>= 1) s += __shfl_xor_sync(0xffffffffu, s, o);
        if ((t & 31) == 0) red8[t >> 5] = s;
        __syncthreads();
        float S = 0.0f;
        #pragma unroll
        for (int i = 0; i < 8; i++) S += red8[i];
        float inv = 1.0f / S;
        #pragma unroll
        for (int i = 0; i < 16; i++) g_prevw[h*N + t + i*256] = v[i] * inv;
    }
}

// ---------------- kernel B: scores = beta * cos(memory, key) ----------------
// Pass 1 over memory. One warp per row, 8 rows/warp (MLP_p1 = 8), 64 rows/block.
// __ldcs: streaming read, no reuse (268 MB >> L2).
// grid = B * N/64 = 8192, 256 threads.
__global__ void score_kernel(const float* __restrict__ memory)
{
    int b    = blockIdx.x >> 6;           // N/64 = 64 blocks per batch
    int n0   = (blockIdx.x & 63) * 64;
    int lane = threadIdx.x & 31;
    int warp = threadIdx.x >> 5;

    // per-lane key slices (fixed w = lane*4 .. +3) and per-head scalars
    const float4* K = (const float4*)g_keys;
    float4 k0 = K[((b*4 + 0)*W >> 2) + lane];
    float4 k1 = K[((b*4 + 1)*W >> 2) + lane];
    float4 k2 = K[((b*4 + 2)*W >> 2) + lane];
    float4 k3 = K[((b*4 + 3)*W >> 2) + lane];
    float be0 = g_beta[b*4+0], be1 = g_beta[b*4+1], be2 = g_beta[b*4+2], be3 = g_beta[b*4+3];
    float kn0 = g_keynorm[b*4+0], kn1 = g_keynorm[b*4+1], kn2 = g_keynorm[b*4+2], kn3 = g_keynorm[b*4+3];

    const float4* M4 = (const float4*)memory;
    int nbase = n0 + warp*8;
    long rowidx = (((long)b*N + nbase) << 5) + lane;

    // front-batch all 8 independent row loads (evict-first)
    float4 mrow[8];
    #pragma unroll
    for (int i = 0; i < 8; i++) mrow[i] = __ldcs(&M4[rowidx + 32*i]);

    #pragma unroll
    for (int r = 0; r < 8; r++) {
        float4 m = mrow[r];
        int n = nbase + r;
        float nn = m.x*m.x + m.y*m.y + m.z*m.z + m.w*m.w;
        float d0 = m.x*k0.x + m.y*k0.y + m.z*k0.z + m.w*k0.w;
        float d1 = m.x*k1.x + m.y*k1.y + m.z*k1.z + m.w*k1.w;
        float d2 = m.x*k2.x + m.y*k2.y + m.z*k2.z + m.w*k2.w;
        float d3 = m.x*k3.x + m.y*k3.y + m.z*k3.z + m.w*k3.w;
        #pragma unroll
        for (int o = 16; o; o >>= 1) {
            nn += __shfl_xor_sync(0xffffffffu, nn, o);
            d0 += __shfl_xor_sync(0xffffffffu, d0, o);
            d1 += __shfl_xor_sync(0xffffffffu, d1, o);
            d2 += __shfl_xor_sync(0xffffffffu, d2, o);
            d3 += __shfl_xor_sync(0xffffffffu, d3, o);
        }
        float mn = sqrtf(nn);
        if (lane < 4) {
            float dd = (lane == 0) ? d0 : (lane == 1) ? d1 : (lane == 2) ? d2 : d3;
            float be = (lane == 0) ? be0 : (lane == 1) ? be1 : (lane == 2) ? be2 : be3;
            float kn = (lane == 0) ? kn0 : (lane == 1) ? kn1 : (lane == 2) ? kn2 : kn3;
            g_scores[(b*4 + lane)*N + n] = be * dd / (kn * mn + EPS);
        }
    }
}

// ---------------- kernel C: write distribution ----------------
// grid = BH blocks (one per (b,h)), 256 threads; 16 elems/thread.
// __powf fast path for the sharpening (rel_err budget: 1e-3, measured 4e-8).
__global__ void wdist_kernel()
{
    int bh = blockIdx.x;
    int h  = bh & 3;
    int t  = threadIdx.x;
    int lane = t & 31, warp = t >> 5;

    __shared__ float sw[N];
    __shared__ float redA[8];
    __shared__ float redB[8];

    const float* sc = g_scores + bh*N;
    float v[16];
    float mx = -INFINITY;
    #pragma unroll
    for (int i = 0; i < 16; i++) { v[i] = sc[t + i*256]; mx = fmaxf(mx, v[i]); }

    // block max
    #pragma unroll
    for (int o = 16; o; o >>= 1) mx = fmaxf(mx, __shfl_xor_sync(0xffffffffu, mx, o));
    if (lane == 0) redA[warp] = mx;
    __syncthreads();
    float M = redA[0];
    #pragma unroll
    for (int i = 1; i < 8; i++) M = fmaxf(M, redA[i]);

    // exp + block sum
    float s = 0.0f;
    #pragma unroll
    for (int i = 0; i < 16; i++) { v[i] = expf(v[i] - M); s += v[i]; }
    #pragma unroll
    for (int o = 16; o; o >>= 1) s += __shfl_xor_sync(0xffffffffu, s, o);
    if (lane == 0) redB[warp] = s;
    __syncthreads();
    float S = 0.0f;
    #pragma unroll
    for (int i = 0; i < 8; i++) S += redB[i];
    float invS = 1.0f / S;

    float g  = g_gate[bh];
    float og = 1.0f - g;
    #pragma unroll
    for (int i = 0; i < 16; i++) {
        int n = t + i*256;
        sw[n] = g * v[i] * invS + og * g_prevw[h*N + n];
    }
    __syncthreads();

    float s0 = g_shift[bh*3 + 0], s1 = g_shift[bh*3 + 1], s2 = g_shift[bh*3 + 2];
    float gamma = g_gamma[bh];
    float T = 0.0f;
    #pragma unroll
    for (int i = 0; i < 16; i++) {
        int n = t + i*256;
        float ws = s0 * sw[(n + N - 1) & (N - 1)] + s1 * sw[n] + s2 * sw[(n + 1) & (N - 1)];
        v[i] = __powf(ws, gamma);     // fast path: base strictly positive
        T += v[i];
    }
    #pragma unroll
    for (int o = 16; o; o >>= 1) T += __shfl_xor_sync(0xffffffffu, T, o);
    __syncthreads();           // redA reuse safe (everyone done reading M)
    if (lane == 0) redA[warp] = T;
    __syncthreads();
    float TT = 0.0f;
    #pragma unroll
    for (int i = 0; i < 8; i++) TT += redA[i];
    float invT = 1.0f / (TT + EPS);
    #pragma unroll
    for (int i = 0; i < 16; i++) g_wdist[bh*N + t + i*256] = v[i] * invT;
}

// ---------------- kernel D: memory update (erase + add) ----------------
// Pass 2 over memory. One warp per row, 4 rows/warp, 32 rows/block.
// erase/write slices live in registers; __ldcs reads + __stcs writes (no reuse).
// grid = B * N/32 = 16384, 256 threads.
__global__ void update_kernel(const float* __restrict__ memory, float* __restrict__ out)
{
    int b    = blockIdx.x >> 7;
    int n0   = (blockIdx.x & 127) * 32;
    int lane = threadIdx.x & 31;
    int warp = threadIdx.x >> 5;

    const float4* E = (const float4*)g_erase;
    const float4* Wd = (const float4*)g_write;
    float4 e0 = E[((b*4+0)*W >> 2) + lane];
    float4 e1 = E[((b*4+1)*W >> 2) + lane];
    float4 e2 = E[((b*4+2)*W >> 2) + lane];
    float4 e3 = E[((b*4+3)*W >> 2) + lane];
    float4 w0 = Wd[((b*4+0)*W >> 2) + lane];
    float4 w1 = Wd[((b*4+1)*W >> 2) + lane];
    float4 w2 = Wd[((b*4+2)*W >> 2) + lane];
    float4 w3 = Wd[((b*4+3)*W >> 2) + lane];

    const float4* M4 = (const float4*)memory;
    float4*       O4 = (float4*)out;

    int nbase = n0 + warp*4;
    long rowidx = (((long)b*N + nbase) << 5) + lane;

    // front-batch the 4 memory row loads (evict-first)
    float4 mrow[4];
    #pragma unroll
    for (int i = 0; i < 4; i++) mrow[i] = __ldcs(&M4[rowidx + 32*i]);

    // front-batch the 16 wdist scalars
    float wdv[4][4];
    #pragma unroll
    for (int r = 0; r < 4; r++) {
        int n = nbase + r;
        wdv[r][0] = g_wdist[(b*4+0)*N + n];
        wdv[r][1] = g_wdist[(b*4+1)*N + n];
        wdv[r][2] = g_wdist[(b*4+2)*N + n];
        wdv[r][3] = g_wdist[(b*4+3)*N + n];
    }

    #pragma unroll
    for (int r = 0; r < 4; r++) {
        float wd0 = wdv[r][0], wd1 = wdv[r][1], wd2 = wdv[r][2], wd3 = wdv[r][3];
        float4 m = mrow[r];
        float4 o;
        {
            float er = (1.0f - wd0*e0.x)*(1.0f - wd1*e1.x)*(1.0f - wd2*e2.x)*(1.0f - wd3*e3.x);
            float up = wd0*w0.x + wd1*w1.x + wd2*w2.x + wd3*w3.x;
            o.x = m.x*er + up;
        }
        {
            float er = (1.0f - wd0*e0.y)*(1.0f - wd1*e1.y)*(1.0f - wd2*e2.y)*(1.0f - wd3*e3.y);
            float up = wd0*w0.y + wd1*w1.y + wd2*w2.y + wd3*w3.y;
            o.y = m.y*er + up;
        }
        {
            float er = (1.0f - wd0*e0.z)*(1.0f - wd1*e1.z)*(1.0f - wd2*e2.z)*(1.0f - wd3*e3.z);
            float up = wd0*w0.z + wd1*w1.z + wd2*w2.z + wd3*w3.z;
            o.z = m.z*er + up;
        }
        {
            float er = (1.0f - wd0*e0.w)*(1.0f - wd1*e1.w)*(1.0f - wd2*e2.w)*(1.0f - wd3*e3.w);
            float up = wd0*w0.w + wd1*w1.w + wd2*w2.w + wd3*w3.w;
            o.w = m.w*er + up;
        }
        __stcs(&O4[rowidx + r*32], o);
    }
}

// ---------------- launch ----------------
extern "C" void kernel_launch(void* const* d_in, const int* in_sizes, int n_in,
                              void* d_out, int out_size)
{
    const float* memory   = (const float*)d_in[0];
    const float* controls = (const float*)d_in[1];
    const float* bias     = (const float*)d_in[2];
    float* out = (float*)d_out;

    prep_all_kernel<<<BH + H, 256>>>(controls, bias);
    score_kernel   <<<B * (N/64), 256>>>(memory);
    wdist_kernel   <<<BH, 256>>>();
    update_kernel  <<<B * (N/32), 256>>>(memory, out);
}